// round 1
// baseline (speedup 1.0000x reference)
#include <cuda_runtime.h>
#include <math.h>

#define RES 256
#define W 256
#define H 256
#define MAX_SAMPLES 384
#define TF_RES 128
#define NEAR_T 0.1f
#define FAR_T 100.0f
#define HIT_EPS 1e-3f

struct V3 { float x, y, z; };

__device__ __forceinline__ V3 v3(float x, float y, float z) { V3 r; r.x=x; r.y=y; r.z=z; return r; }
__device__ __forceinline__ V3 vadd(V3 a, V3 b) { return v3(a.x+b.x, a.y+b.y, a.z+b.z); }
__device__ __forceinline__ V3 vscale(V3 a, float s) { return v3(a.x*s, a.y*s, a.z*s); }
__device__ __forceinline__ V3 vcross(V3 a, V3 b) {
    return v3(a.y*b.z - a.z*b.y, a.z*b.x - a.x*b.z, a.x*b.y - a.y*b.x);
}
__device__ __forceinline__ V3 vnorm(V3 a) {
    float inv = rsqrtf(a.x*a.x + a.y*a.y + a.z*a.z);
    return vscale(a, inv);
}

__global__ void __launch_bounds__(256, 4)
raycast_kernel(const float* __restrict__ vol,
               const float* __restrict__ tf,
               const float* __restrict__ cam_in,
               const int*   __restrict__ sr_in,
               float* __restrict__ out)
{
    __shared__ float4 s_tf[TF_RES];
    int tid = threadIdx.x;
    if (tid < TF_RES) s_tf[tid] = reinterpret_cast<const float4*>(tf)[tid];
    __syncthreads();

    int w = blockIdx.x;
    int h = tid;

    // --- decode sampling rate (robust to int32 or float32 storage) ---
    int raw = sr_in[0];
    float sr;
    if (raw >= 1 && raw <= 4096) {
        sr = (float)raw;
    } else {
        float f = __int_as_float(raw);
        sr = (f > 0.0f && f <= 4096.0f) ? f : 1.0f;
    }
    float inv_sr = 1.0f / sr;
    bool sr_is_one = (sr == 1.0f);

    V3 cam = v3(cam_in[0], cam_in[1], cam_in[2]);

    // camera basis
    V3 fwd = vnorm(v3(-cam.x, -cam.y, -cam.z));
    V3 right = vnorm(v3(-fwd.z, 0.0f, fwd.x));       // cross(fwd, (0,1,0))
    V3 up = vcross(right, fwd);

    const float tanf_half = 0.2679491924311227f;      // tan(15 deg)
    float u = ((w + 0.5f) / (float)W * 2.0f - 1.0f) * tanf_half; // aspect = 1
    float v = ((h + 0.5f) / (float)H * 2.0f - 1.0f) * tanf_half;

    V3 dir = vnorm(vadd(fwd, vadd(vscale(right, u), vscale(up, v))));

    // ray vs [-1,1]^3
    float ix = 1.0f / dir.x, iy = 1.0f / dir.y, iz = 1.0f / dir.z;
    float tx0 = (-1.0f - cam.x) * ix, tx1 = (1.0f - cam.x) * ix;
    float ty0 = (-1.0f - cam.y) * iy, ty1 = (1.0f - cam.y) * iy;
    float tz0 = (-1.0f - cam.z) * iz, tz1 = (1.0f - cam.z) * iz;
    float tmin = fmaxf(fmaxf(fminf(tx0, tx1), fminf(ty0, ty1)), fminf(tz0, tz1));
    float tmax = fminf(fminf(fmaxf(tx0, tx1), fmaxf(ty0, ty1)), fmaxf(tz0, tz1));
    bool hit = (tmax >= 0.0f) && (tmin <= tmax);

    float rr = 0.0f, gg = 0.0f, bb = 0.0f, acc = 0.0f;
    float depth = 1.0f;

    if (hit) {
        float entry = fmaxf(tmin, NEAR_T);
        float dist = fmaxf(tmax - entry, 0.0f);
        float ns = ceilf(dist * 0.5f * (float)RES * sr);
        ns = fminf(fmaxf(ns, 1.0f), (float)MAX_SAMPLES);
        float step = dist / ns;
        int n = (int)ns;

        float T = 1.0f;
        bool any_hit = false;
        float t_first = 0.0f;

        for (int k = 0; k < n; k++) {
            float t = entry + ((float)k + 0.5f) * step;
            float px = cam.x + t * dir.x;
            float py = cam.y + t * dir.y;
            float pz = cam.z + t * dir.z;
            // to voxel coords, clamp to [0, 255]
            float qx = fminf(fmaxf((px * 0.5f + 0.5f) * 255.0f, 0.0f), 255.0f);
            float qy = fminf(fmaxf((py * 0.5f + 0.5f) * 255.0f, 0.0f), 255.0f);
            float qz = fminf(fmaxf((pz * 0.5f + 0.5f) * 255.0f, 0.0f), 255.0f);
            int x0 = (int)qx, y0 = (int)qy, z0 = (int)qz;
            float fx = qx - (float)x0;
            float fy = qy - (float)y0;
            float fz = qz - (float)z0;
            int dx = (x0 < RES - 1) ? RES * RES : 0;
            int dy = (y0 < RES - 1) ? RES : 0;
            int dz = (z0 < RES - 1) ? 1 : 0;
            int base = ((x0 << 8) + y0 << 8) + z0;

            float c000 = __ldg(vol + base);
            float c001 = __ldg(vol + base + dz);
            float c010 = __ldg(vol + base + dy);
            float c011 = __ldg(vol + base + dy + dz);
            float c100 = __ldg(vol + base + dx);
            float c101 = __ldg(vol + base + dx + dz);
            float c110 = __ldg(vol + base + dx + dy);
            float c111 = __ldg(vol + base + dx + dy + dz);

            // lerp x, then y, then z (matches reference order)
            float c00 = c000 + fx * (c100 - c000);
            float c10 = c010 + fx * (c110 - c010);
            float c01 = c001 + fx * (c101 - c001);
            float c11 = c011 + fx * (c111 - c011);
            float c0 = c00 + fy * (c10 - c00);
            float c1 = c01 + fy * (c11 - c01);
            float intensity = c0 + fz * (c1 - c0);

            // TF lookup
            float xi = fminf(fmaxf(intensity, 0.0f), 1.0f) * (float)(TF_RES - 1);
            int l = (int)xi;
            float f = xi - (float)l;
            int hi2 = min(l + 1, TF_RES - 1);
            float4 ca = s_tf[l];
            float4 cb = s_tf[hi2];
            float cr = ca.x + f * (cb.x - ca.x);
            float cg = ca.y + f * (cb.y - ca.y);
            float cbv = ca.z + f * (cb.z - ca.z);
            float a = ca.w + f * (cb.w - ca.w);

            if (!sr_is_one) a = 1.0f - powf(1.0f - a, inv_sr);

            float wgt = T * a;
            rr += wgt * cr;
            gg += wgt * cg;
            bb += wgt * cbv;
            acc += wgt;
            T *= (1.0f - a);

            if (!any_hit && a > HIT_EPS) { any_hit = true; t_first = t; }
            // Early termination: remaining contribution bounded by T < 1e-6,
            // and first-hit is provably already found at this point
            // ((1-1e-3)^384 >> 1e-6, so T<1e-6 implies some a > 1e-3 occurred).
            if (T < 1e-6f) break;
        }

        if (any_hit) depth = (t_first - NEAR_T) / (FAR_T - NEAR_T);
    }

    float* o = out + ((size_t)w * H + h) * 5;
    o[0] = rr;
    o[1] = gg;
    o[2] = bb;
    o[3] = acc;
    o[4] = depth;
}

extern "C" void kernel_launch(void* const* d_in, const int* in_sizes, int n_in,
                              void* d_out, int out_size)
{
    const float* vol = (const float*)d_in[0];
    const float* tf  = (const float*)d_in[1];
    const float* cam = (const float*)d_in[2];
    const int*   sr  = (const int*)d_in[3];
    float* out = (float*)d_out;
    raycast_kernel<<<W, H>>>(vol, tf, cam, sr, out);
}